// round 14
// baseline (speedup 1.0000x reference)
#include <cuda_runtime.h>
#include <cuda_bf16.h>
#include <cstdint>

#define N_NODES 50000
#define N_EDGES 800000
#define IN_FEAT 512
#define HIDDEN  64
#define N_CLASS 16

#define KC2   32                    // K per chunk
#define KPAD  40                    // padded row (80B stride -> conflict-free LDSM)
#define RBM   64                    // rows per CTA in gemm1
#define NCHUNK2 (IN_FEAT / KC2)     // 16

// Scratch (device globals — no allocation allowed)
__device__ float g_h0[N_NODES * HIDDEN];   // x @ W1
__device__ float g_h [N_NODES * HIDDEN];   // A @ h0 + b1 (pre-relu)
__device__ float g_z [N_NODES * N_CLASS];  // relu(h) @ W2
__device__ float g_l [N_NODES * N_CLASS];  // A @ z + b2 (logits)
__device__ __nv_bfloat16 g_w1t_hi[HIDDEN * IN_FEAT];  // W1^T hi, [n][k]
__device__ __nv_bfloat16 g_w1t_lo[HIDDEN * IN_FEAT];  // W1^T residual

__device__ __forceinline__ void red_add_v4(float* p, float4 v) {
    asm volatile("red.global.add.v4.f32 [%0], {%1,%2,%3,%4};"
                 :: "l"(p), "f"(v.x), "f"(v.y), "f"(v.z), "f"(v.w)
                 : "memory");
}

__device__ __forceinline__ uint32_t pack_bf2(float v0, float v1) {
    uint32_t r;
    asm("cvt.rn.bf16x2.f32 %0, %1, %2;" : "=r"(r) : "f"(v1), "f"(v0));
    return r;
}
__device__ __forceinline__ float bf_round(float v) {
    return __bfloat162float(__float2bfloat16_rn(v));
}

__device__ __forceinline__ uint32_t smem_u32(const void* p) {
    uint32_t a;
    asm("{ .reg .u64 t; cvta.to.shared.u64 t, %1; cvt.u32.u64 %0, t; }"
        : "=r"(a) : "l"(p));
    return a;
}

__device__ __forceinline__ void mma_bf16(float* d, const uint32_t* a,
                                         uint32_t b0, uint32_t b1) {
    asm("mma.sync.aligned.m16n8k16.row.col.f32.bf16.bf16.f32 "
        "{%0,%1,%2,%3}, {%4,%5,%6,%7}, {%8,%9}, {%0,%1,%2,%3};"
        : "+f"(d[0]), "+f"(d[1]), "+f"(d[2]), "+f"(d[3])
        : "r"(a[0]), "r"(a[1]), "r"(a[2]), "r"(a[3]), "r"(b0), "r"(b1));
}

#define LDSM4(r0, r1, r2, r3, addr) \
    asm volatile("ldmatrix.sync.aligned.m8n8.x4.shared.b16 {%0,%1,%2,%3}, [%4];" \
                 : "=r"(r0), "=r"(r1), "=r"(r2), "=r"(r3) : "r"(addr))

// ---------------------------------------------------------------------------
// init_h: g_h <- broadcast b1                       (launch #1)
// ---------------------------------------------------------------------------
__global__ void init_h_kernel(const float* __restrict__ b1) {
    int i = blockIdx.x * blockDim.x + threadIdx.x;
    if (i < N_NODES * HIDDEN) g_h[i] = b1[i & (HIDDEN - 1)];
}

// ---------------------------------------------------------------------------
// init_l: g_l <- broadcast b2                       (launch #2)
// ---------------------------------------------------------------------------
__global__ void init_l_kernel(const float* __restrict__ b2) {
    int i = blockIdx.x * blockDim.x + threadIdx.x;
    if (i < N_NODES * N_CLASS) g_l[i] = b2[i & (N_CLASS - 1)];
}

// ---------------------------------------------------------------------------
// w1t: W1[k][n] fp32 -> g_w1t_{hi,lo}[n][k] bf16    (launch #3)
// ---------------------------------------------------------------------------
__global__ void w1t_kernel(const float* __restrict__ W1) {
    int i = blockIdx.x * blockDim.x + threadIdx.x;
    if (i >= IN_FEAT * HIDDEN) return;
    int k = i >> 6;
    int n = i & 63;
    float v = W1[i];
    __nv_bfloat16 h = __float2bfloat16_rn(v);
    float r = v - __bfloat162float(h);
    g_w1t_hi[(size_t)n * IN_FEAT + k] = h;
    g_w1t_lo[(size_t)n * IN_FEAT + k] = __float2bfloat16_rn(r);
}

// ---------------------------------------------------------------------------
// GEMM1: g_h0 = x @ W1  via mma.sync bf16 (3-term split) + ldmatrix  (#4)
// CTA: 256 thr = 8 warps. Tile M=64, N=64. grid=782.   (round-11 build)
// ---------------------------------------------------------------------------
__global__ __launch_bounds__(256, 3)
void gemm1_kernel(const float* __restrict__ x) {
    __shared__ __align__(16) __nv_bfloat16 Ah[2][RBM * KPAD];     // 2x5 KB
    __shared__ __align__(16) __nv_bfloat16 Al[2][RBM * KPAD];     // 2x5 KB
    __shared__ __align__(16) __nv_bfloat16 Bh[2][HIDDEN * KPAD];  // 2x5 KB
    __shared__ __align__(16) __nv_bfloat16 Bl[2][HIDDEN * KPAD];  // 2x5 KB

    const int tid  = threadIdx.x;
    const int wid  = tid >> 5;
    const int lane = tid & 31;
    const int g    = lane >> 2;
    const int tig  = lane & 3;
    const int rg   = wid & 3;
    const int cg   = wid >> 2;
    const int row0 = blockIdx.x * RBM;

    const int arow = tid >> 2;
    const int aseg = tid & 3;
    int grow = row0 + arow;
    if (grow >= N_NODES) grow = N_NODES - 1;
    const float* xrow = x + (size_t)grow * IN_FEAT + aseg * 8;

    const int bn  = tid >> 2;
    const int bsg = tid & 3;

    const uint32_t bufStride = RBM * KPAD * 2;   // 5120 B
    const int a_row_l = rg * 16 + (lane & 7) + ((lane >> 3) & 1) * 8;
    const int a_koff  = (lane >> 4) * 8;
    const uint32_t aAh = smem_u32(&Ah[0][0]) + (a_row_l * KPAD + a_koff) * 2;
    const uint32_t aAl = smem_u32(&Al[0][0]) + (a_row_l * KPAD + a_koff) * 2;
    uint32_t aBh[2], aBl[2];
    #pragma unroll
    for (int p = 0; p < 2; p++) {
        int nrow = (cg * 4 + 2 * p + (lane >> 4)) * 8 + (lane & 7);
        int koff = ((lane >> 3) & 1) * 8;
        aBh[p] = smem_u32(&Bh[0][0]) + (nrow * KPAD + koff) * 2;
        aBl[p] = smem_u32(&Bl[0][0]) + (nrow * KPAD + koff) * 2;
    }

    float4 xr[2];
    uint4  bwh, bwl;

    auto ld = [&](int c) {
        const int k0 = c * KC2;
        xr[0] = __ldg(reinterpret_cast<const float4*>(&xrow[k0]));
        xr[1] = __ldg(reinterpret_cast<const float4*>(&xrow[k0 + 4]));
        bwh = *reinterpret_cast<const uint4*>(
                  &g_w1t_hi[(size_t)bn * IN_FEAT + k0 + bsg * 8]);
        bwl = *reinterpret_cast<const uint4*>(
                  &g_w1t_lo[(size_t)bn * IN_FEAT + k0 + bsg * 8]);
    };
    auto st = [&](int b) {
        #pragma unroll
        for (int q = 0; q < 2; q++) {
            float4 v = xr[q];
            uint2 hv = make_uint2(pack_bf2(v.x, v.y), pack_bf2(v.z, v.w));
            uint2 lv = make_uint2(
                pack_bf2(v.x - bf_round(v.x), v.y - bf_round(v.y)),
                pack_bf2(v.z - bf_round(v.z), v.w - bf_round(v.w)));
            int eo = arow * KPAD + aseg * 8 + q * 4;
            *reinterpret_cast<uint2*>(&Ah[b][eo]) = hv;
            *reinterpret_cast<uint2*>(&Al[b][eo]) = lv;
        }
        *reinterpret_cast<uint4*>(&Bh[b][bn * KPAD + bsg * 8]) = bwh;
        *reinterpret_cast<uint4*>(&Bl[b][bn * KPAD + bsg * 8]) = bwl;
    };

    float d[4][4] = {};

    ld(0); st(0);
    __syncthreads();

    for (int c = 0; c < NCHUNK2; c++) {
        const int cb = c & 1;
        const uint32_t bo = cb * bufStride;
        if (c + 1 < NCHUNK2) ld(c + 1);

        #pragma unroll
        for (int ks = 0; ks < 2; ks++) {
            const uint32_t ko = ks * 32;
            uint32_t ah[4], al[4];
            LDSM4(ah[0], ah[1], ah[2], ah[3], aAh + bo + ko);
            LDSM4(al[0], al[1], al[2], al[3], aAl + bo + ko);
            #pragma unroll
            for (int p = 0; p < 2; p++) {
                uint32_t bh0, bh1, bh2, bh3, bl0, bl1, bl2, bl3;
                LDSM4(bh0, bh1, bh2, bh3, aBh[p] + bo + ko);
                LDSM4(bl0, bl1, bl2, bl3, aBl[p] + bo + ko);
                mma_bf16(d[2*p],     ah, bh0, bh1);
                mma_bf16(d[2*p],     al, bh0, bh1);
                mma_bf16(d[2*p],     ah, bl0, bl1);
                mma_bf16(d[2*p + 1], ah, bh2, bh3);
                mma_bf16(d[2*p + 1], al, bh2, bh3);
                mma_bf16(d[2*p + 1], ah, bl2, bl3);
            }
        }

        if (c + 1 < NCHUNK2) st(1 - cb);
        __syncthreads();
    }

    {
        int r0 = row0 + rg * 16 + g;
        int r1 = r0 + 8;
        #pragma unroll
        for (int j = 0; j < 4; j++) {
            int col = (cg * 4 + j) * 8 + 2 * tig;
            if (r0 < N_NODES)
                *reinterpret_cast<float2*>(&g_h0[(size_t)r0 * HIDDEN + col]) =
                    make_float2(d[j][0], d[j][1]);
            if (r1 < N_NODES)
                *reinterpret_cast<float2*>(&g_h0[(size_t)r1 * HIDDEN + col]) =
                    make_float2(d[j][2], d[j][3]);
        }
    }
}

// ---------------------------------------------------------------------------
// SpMM1: g_h[dst] += ew * g_h0[src]
// 8 lanes/edge, 2x float4 per thread: halves metadata-load redundancy.
// ---------------------------------------------------------------------------
__global__ __launch_bounds__(256)
void spmm1_kernel(const int* __restrict__ src, const int* __restrict__ dst,
                  const float* __restrict__ ew) {
    int t = blockIdx.x * blockDim.x + threadIdx.x;
    int e = t >> 3;
    int f = (t & 7) << 3;      // 8 floats = 32B per thread
    if (e >= N_EDGES) return;
    int s   = __ldg(&src[e]);
    int d   = __ldg(&dst[e]);
    float w = __ldg(&ew[e]);
    const float4* vp = reinterpret_cast<const float4*>(&g_h0[(size_t)s * HIDDEN + f]);
    float4 v0 = vp[0];
    float4 v1 = vp[1];
    float* op = &g_h[(size_t)d * HIDDEN + f];
    red_add_v4(op,     make_float4(v0.x * w, v0.y * w, v0.z * w, v0.w * w));
    red_add_v4(op + 4, make_float4(v1.x * w, v1.y * w, v1.z * w, v1.w * w));
}

// ---------------------------------------------------------------------------
// GEMM2: g_z = relu(g_h) @ W2   (50000x64 @ 64x16), thread per node.
// ---------------------------------------------------------------------------
__global__ __launch_bounds__(64)
void gemm2_kernel(const float* __restrict__ W2) {
    __shared__ float4 Ws[HIDDEN][N_CLASS / 4];   // 4 KB

    const int tid = threadIdx.x;
    #pragma unroll
    for (int j = 0; j < 4; j++) {
        int i = tid + j * 64;
        int kk = i >> 2, qq = i & 3;
        Ws[kk][qq] = reinterpret_cast<const float4*>(&W2[(size_t)kk * N_CLASS])[qq];
    }
    __syncthreads();

    int n = blockIdx.x * 64 + tid;
    if (n >= N_NODES) return;

    float acc[N_CLASS] = {};
    const float4* hrow = reinterpret_cast<const float4*>(&g_h[(size_t)n * HIDDEN]);
    #pragma unroll
    for (int kq = 0; kq < HIDDEN / 4; kq++) {
        float4 h4 = __ldg(&hrow[kq]);
        float hv[4] = {fmaxf(h4.x, 0.f), fmaxf(h4.y, 0.f),
                       fmaxf(h4.z, 0.f), fmaxf(h4.w, 0.f)};
        #pragma unroll
        for (int j = 0; j < 4; j++) {
            int k = kq * 4 + j;
            #pragma unroll
            for (int q = 0; q < 4; q++) {
                float4 w4 = Ws[k][q];
                acc[q * 4 + 0] = fmaf(hv[j], w4.x, acc[q * 4 + 0]);
                acc[q * 4 + 1] = fmaf(hv[j], w4.y, acc[q * 4 + 1]);
                acc[q * 4 + 2] = fmaf(hv[j], w4.z, acc[q * 4 + 2]);
                acc[q * 4 + 3] = fmaf(hv[j], w4.w, acc[q * 4 + 3]);
            }
        }
    }
    float4* o = reinterpret_cast<float4*>(&g_z[(size_t)n * N_CLASS]);
    #pragma unroll
    for (int q = 0; q < 4; q++)
        o[q] = make_float4(acc[q * 4], acc[q * 4 + 1], acc[q * 4 + 2], acc[q * 4 + 3]);
}

// ---------------------------------------------------------------------------
// SpMM2: g_l[dst] += ew * g_z[src]
// 2 lanes/edge, 2x float4 per thread: halves metadata-load redundancy.
// ---------------------------------------------------------------------------
__global__ __launch_bounds__(256)
void spmm2_kernel(const int* __restrict__ src, const int* __restrict__ dst,
                  const float* __restrict__ ew) {
    int t = blockIdx.x * blockDim.x + threadIdx.x;
    int e = t >> 1;
    int c = (t & 1) << 3;      // 8 floats = 32B per thread
    if (e >= N_EDGES) return;
    int s   = __ldg(&src[e]);
    int d   = __ldg(&dst[e]);
    float w = __ldg(&ew[e]);
    const float4* vp = reinterpret_cast<const float4*>(&g_z[(size_t)s * N_CLASS + c]);
    float4 v0 = vp[0];
    float4 v1 = vp[1];
    float* op = &g_l[(size_t)d * N_CLASS + c];
    red_add_v4(op,     make_float4(v0.x * w, v0.y * w, v0.z * w, v0.w * w));
    red_add_v4(op + 4, make_float4(v1.x * w, v1.y * w, v1.z * w, v1.w * w));
}

// ---------------------------------------------------------------------------
// Softmax over 16 classes, one thread per node.
// ---------------------------------------------------------------------------
__global__ __launch_bounds__(256)
void softmax_kernel(float* __restrict__ out) {
    int n = blockIdx.x * blockDim.x + threadIdx.x;
    if (n >= N_NODES) return;
    float v[N_CLASS];
    const float4* p = reinterpret_cast<const float4*>(&g_l[(size_t)n * N_CLASS]);
    #pragma unroll
    for (int i = 0; i < 4; i++) {
        float4 q = p[i];
        v[i * 4 + 0] = q.x; v[i * 4 + 1] = q.y; v[i * 4 + 2] = q.z; v[i * 4 + 3] = q.w;
    }
    float m = v[0];
    #pragma unroll
    for (int i = 1; i < N_CLASS; i++) m = fmaxf(m, v[i]);
    float sum = 0.f;
    #pragma unroll
    for (int i = 0; i < N_CLASS; i++) { v[i] = __expf(v[i] - m); sum += v[i]; }
    float inv = 1.f / sum;
    float4* o = reinterpret_cast<float4*>(&out[(size_t)n * N_CLASS]);
    #pragma unroll
    for (int i = 0; i < 4; i++) {
        o[i] = make_float4(v[i * 4] * inv, v[i * 4 + 1] * inv,
                           v[i * 4 + 2] * inv, v[i * 4 + 3] * inv);
    }
}

// ---------------------------------------------------------------------------
extern "C" void kernel_launch(void* const* d_in, const int* in_sizes, int n_in,
                              void* d_out, int out_size) {
    const float* x   = (const float*)d_in[0];
    const int*   src = (const int*)  d_in[1];
    const int*   dst = (const int*)  d_in[2];
    const float* ew  = (const float*)d_in[3];
    const float* W1  = (const float*)d_in[4];
    const float* b1  = (const float*)d_in[5];
    const float* W2  = (const float*)d_in[6];
    const float* b2  = (const float*)d_in[7];
    float* out = (float*)d_out;

    // #1, #2: bias broadcasts
    init_h_kernel<<<(N_NODES * HIDDEN + 255) / 256, 256>>>(b1);
    init_l_kernel<<<(N_NODES * N_CLASS + 255) / 256, 256>>>(b2);
    // #3: W1 transpose + bf16 split
    w1t_kernel<<<(IN_FEAT * HIDDEN + 255) / 256, 256>>>(W1);

    // #4  (profiled slot)
    gemm1_kernel<<<(N_NODES + RBM - 1) / RBM, 256>>>(x);

    // #5
    {
        long long threads = (long long)N_EDGES * 8;
        spmm1_kernel<<<(unsigned)((threads + 255) / 256), 256>>>(src, dst, ew);
    }
    // #6
    gemm2_kernel<<<(N_NODES + 63) / 64, 64>>>(W2);
    // #7
    {
        long long threads = (long long)N_EDGES * 2;
        spmm2_kernel<<<(unsigned)((threads + 255) / 256), 256>>>(src, dst, ew);
    }
    // #8
    softmax_kernel<<<(N_NODES + 255) / 256, 256>>>(out);
}

// round 15
// speedup vs baseline: 1.0815x; 1.0815x over previous
#include <cuda_runtime.h>
#include <cuda_bf16.h>
#include <cstdint>

#define N_NODES 50000
#define N_EDGES 800000
#define IN_FEAT 512
#define HIDDEN  64
#define N_CLASS 16

#define KC2   32                    // K per chunk
#define KPAD  40                    // padded row (80B stride -> conflict-free LDSM)
#define RBM   64                    // rows per CTA in gemm1
#define NCHUNK2 (IN_FEAT / KC2)     // 16

// Scratch (device globals — no allocation allowed)
__device__ float g_h0[N_NODES * HIDDEN];   // x @ W1
__device__ float g_h [N_NODES * HIDDEN];   // A @ h0 + b1 (pre-relu)
__device__ float g_z [N_NODES * N_CLASS];  // relu(h) @ W2
__device__ float g_l [N_NODES * N_CLASS];  // A @ z + b2 (logits)
__device__ __nv_bfloat16 g_w1t_hi[HIDDEN * IN_FEAT];  // W1^T hi, [n][k]
__device__ __nv_bfloat16 g_w1t_lo[HIDDEN * IN_FEAT];  // W1^T residual

__device__ __forceinline__ void red_add_v4(float* p, float4 v) {
    asm volatile("red.global.add.v4.f32 [%0], {%1,%2,%3,%4};"
                 :: "l"(p), "f"(v.x), "f"(v.y), "f"(v.z), "f"(v.w)
                 : "memory");
}

__device__ __forceinline__ uint32_t pack_bf2(float v0, float v1) {
    uint32_t r;
    asm("cvt.rn.bf16x2.f32 %0, %1, %2;" : "=r"(r) : "f"(v1), "f"(v0));
    return r;
}
__device__ __forceinline__ float bf_round(float v) {
    return __bfloat162float(__float2bfloat16_rn(v));
}

__device__ __forceinline__ uint32_t smem_u32(const void* p) {
    uint32_t a;
    asm("{ .reg .u64 t; cvta.to.shared.u64 t, %1; cvt.u32.u64 %0, t; }"
        : "=r"(a) : "l"(p));
    return a;
}

__device__ __forceinline__ void mma_bf16(float* d, const uint32_t* a,
                                         uint32_t b0, uint32_t b1) {
    asm("mma.sync.aligned.m16n8k16.row.col.f32.bf16.bf16.f32 "
        "{%0,%1,%2,%3}, {%4,%5,%6,%7}, {%8,%9}, {%0,%1,%2,%3};"
        : "+f"(d[0]), "+f"(d[1]), "+f"(d[2]), "+f"(d[3])
        : "r"(a[0]), "r"(a[1]), "r"(a[2]), "r"(a[3]), "r"(b0), "r"(b1));
}

#define LDSM4(r0, r1, r2, r3, addr) \
    asm volatile("ldmatrix.sync.aligned.m8n8.x4.shared.b16 {%0,%1,%2,%3}, [%4];" \
                 : "=r"(r0), "=r"(r1), "=r"(r2), "=r"(r3) : "r"(addr))

// ---------------------------------------------------------------------------
// prep: g_h <- b1 broadcast, g_l <- b2 broadcast, W1 -> bf16 hi/lo transpose
// One launch (#1) replaces three.
// ---------------------------------------------------------------------------
__global__ void prep_kernel(const float* __restrict__ b1,
                            const float* __restrict__ b2,
                            const float* __restrict__ W1) {
    int i = blockIdx.x * blockDim.x + threadIdx.x;
    if (i < N_NODES * HIDDEN) g_h[i] = b1[i & (HIDDEN - 1)];
    if (i < N_NODES * N_CLASS) g_l[i] = b2[i & (N_CLASS - 1)];
    if (i < IN_FEAT * HIDDEN) {
        int k = i >> 6;
        int n = i & 63;
        float v = W1[i];
        __nv_bfloat16 h = __float2bfloat16_rn(v);
        float r = v - __bfloat162float(h);
        g_w1t_hi[(size_t)n * IN_FEAT + k] = h;
        g_w1t_lo[(size_t)n * IN_FEAT + k] = __float2bfloat16_rn(r);
    }
}

// ---------------------------------------------------------------------------
// GEMM1: g_h0 = x @ W1  via mma.sync bf16 (3-term split) + ldmatrix  (#2)
// CTA: 256 thr = 8 warps. Tile M=64, N=64. grid=782.   (round-11 build)
// ---------------------------------------------------------------------------
__global__ __launch_bounds__(256, 3)
void gemm1_kernel(const float* __restrict__ x) {
    __shared__ __align__(16) __nv_bfloat16 Ah[2][RBM * KPAD];     // 2x5 KB
    __shared__ __align__(16) __nv_bfloat16 Al[2][RBM * KPAD];     // 2x5 KB
    __shared__ __align__(16) __nv_bfloat16 Bh[2][HIDDEN * KPAD];  // 2x5 KB
    __shared__ __align__(16) __nv_bfloat16 Bl[2][HIDDEN * KPAD];  // 2x5 KB

    const int tid  = threadIdx.x;
    const int wid  = tid >> 5;
    const int lane = tid & 31;
    const int g    = lane >> 2;
    const int tig  = lane & 3;
    const int rg   = wid & 3;
    const int cg   = wid >> 2;
    const int row0 = blockIdx.x * RBM;

    const int arow = tid >> 2;
    const int aseg = tid & 3;
    int grow = row0 + arow;
    if (grow >= N_NODES) grow = N_NODES - 1;
    const float* xrow = x + (size_t)grow * IN_FEAT + aseg * 8;

    const int bn  = tid >> 2;
    const int bsg = tid & 3;

    const uint32_t bufStride = RBM * KPAD * 2;   // 5120 B
    const int a_row_l = rg * 16 + (lane & 7) + ((lane >> 3) & 1) * 8;
    const int a_koff  = (lane >> 4) * 8;
    const uint32_t aAh = smem_u32(&Ah[0][0]) + (a_row_l * KPAD + a_koff) * 2;
    const uint32_t aAl = smem_u32(&Al[0][0]) + (a_row_l * KPAD + a_koff) * 2;
    uint32_t aBh[2], aBl[2];
    #pragma unroll
    for (int p = 0; p < 2; p++) {
        int nrow = (cg * 4 + 2 * p + (lane >> 4)) * 8 + (lane & 7);
        int koff = ((lane >> 3) & 1) * 8;
        aBh[p] = smem_u32(&Bh[0][0]) + (nrow * KPAD + koff) * 2;
        aBl[p] = smem_u32(&Bl[0][0]) + (nrow * KPAD + koff) * 2;
    }

    float4 xr[2];
    uint4  bwh, bwl;

    auto ld = [&](int c) {
        const int k0 = c * KC2;
        xr[0] = __ldg(reinterpret_cast<const float4*>(&xrow[k0]));
        xr[1] = __ldg(reinterpret_cast<const float4*>(&xrow[k0 + 4]));
        bwh = *reinterpret_cast<const uint4*>(
                  &g_w1t_hi[(size_t)bn * IN_FEAT + k0 + bsg * 8]);
        bwl = *reinterpret_cast<const uint4*>(
                  &g_w1t_lo[(size_t)bn * IN_FEAT + k0 + bsg * 8]);
    };
    auto st = [&](int b) {
        #pragma unroll
        for (int q = 0; q < 2; q++) {
            float4 v = xr[q];
            uint2 hv = make_uint2(pack_bf2(v.x, v.y), pack_bf2(v.z, v.w));
            uint2 lv = make_uint2(
                pack_bf2(v.x - bf_round(v.x), v.y - bf_round(v.y)),
                pack_bf2(v.z - bf_round(v.z), v.w - bf_round(v.w)));
            int eo = arow * KPAD + aseg * 8 + q * 4;
            *reinterpret_cast<uint2*>(&Ah[b][eo]) = hv;
            *reinterpret_cast<uint2*>(&Al[b][eo]) = lv;
        }
        *reinterpret_cast<uint4*>(&Bh[b][bn * KPAD + bsg * 8]) = bwh;
        *reinterpret_cast<uint4*>(&Bl[b][bn * KPAD + bsg * 8]) = bwl;
    };

    float d[4][4] = {};

    ld(0); st(0);
    __syncthreads();

    for (int c = 0; c < NCHUNK2; c++) {
        const int cb = c & 1;
        const uint32_t bo = cb * bufStride;
        if (c + 1 < NCHUNK2) ld(c + 1);

        #pragma unroll
        for (int ks = 0; ks < 2; ks++) {
            const uint32_t ko = ks * 32;
            uint32_t ah[4], al[4];
            LDSM4(ah[0], ah[1], ah[2], ah[3], aAh + bo + ko);
            LDSM4(al[0], al[1], al[2], al[3], aAl + bo + ko);
            #pragma unroll
            for (int p = 0; p < 2; p++) {
                uint32_t bh0, bh1, bh2, bh3, bl0, bl1, bl2, bl3;
                LDSM4(bh0, bh1, bh2, bh3, aBh[p] + bo + ko);
                LDSM4(bl0, bl1, bl2, bl3, aBl[p] + bo + ko);
                mma_bf16(d[2*p],     ah, bh0, bh1);
                mma_bf16(d[2*p],     al, bh0, bh1);
                mma_bf16(d[2*p],     ah, bl0, bl1);
                mma_bf16(d[2*p + 1], ah, bh2, bh3);
                mma_bf16(d[2*p + 1], al, bh2, bh3);
                mma_bf16(d[2*p + 1], ah, bl2, bl3);
            }
        }

        if (c + 1 < NCHUNK2) st(1 - cb);
        __syncthreads();
    }

    {
        int r0 = row0 + rg * 16 + g;
        int r1 = r0 + 8;
        #pragma unroll
        for (int j = 0; j < 4; j++) {
            int col = (cg * 4 + j) * 8 + 2 * tig;
            if (r0 < N_NODES)
                *reinterpret_cast<float2*>(&g_h0[(size_t)r0 * HIDDEN + col]) =
                    make_float2(d[j][0], d[j][1]);
            if (r1 < N_NODES)
                *reinterpret_cast<float2*>(&g_h0[(size_t)r1 * HIDDEN + col]) =
                    make_float2(d[j][2], d[j][3]);
        }
    }
}

// ---------------------------------------------------------------------------
// SpMM1: g_h[dst] += ew * g_h0[src]   (64 feats, 16 lanes/edge, float4 RED)
// Round-11 proven version.                                        (#3)
// ---------------------------------------------------------------------------
__global__ __launch_bounds__(256)
void spmm1_kernel(const int* __restrict__ src, const int* __restrict__ dst,
                  const float* __restrict__ ew) {
    int t = blockIdx.x * blockDim.x + threadIdx.x;
    int e = t >> 4;
    int f = (t & 15) << 2;
    if (e >= N_EDGES) return;
    int s   = __ldg(&src[e]);
    int d   = __ldg(&dst[e]);
    float w = __ldg(&ew[e]);
    float4 v = *reinterpret_cast<const float4*>(&g_h0[(size_t)s * HIDDEN + f]);
    red_add_v4(&g_h[(size_t)d * HIDDEN + f],
               make_float4(v.x * w, v.y * w, v.z * w, v.w * w));
}

// ---------------------------------------------------------------------------
// GEMM2: g_z = relu(g_h) @ W2   (50000x64 @ 64x16)                (#4)
// Output-split: thread (n, half) computes classes half*8..half*8+7 with the
// full k=64 loop. 100k independent threads, no shuffle, 2x warps in flight.
// ---------------------------------------------------------------------------
__global__ __launch_bounds__(256)
void gemm2_kernel(const float* __restrict__ W2) {
    __shared__ float4 Ws[HIDDEN][N_CLASS / 4];   // 4 KB

    const int tid = threadIdx.x;
    {
        int kk = tid >> 2, qq = tid & 3;
        Ws[kk][qq] = reinterpret_cast<const float4*>(&W2[(size_t)kk * N_CLASS])[qq];
    }
    __syncthreads();

    int t2   = blockIdx.x * 256 + tid;
    int n    = t2 >> 1;
    int half = t2 & 1;
    if (n >= N_NODES) return;

    float acc[8] = {};
    const int q0 = half * 2;            // float4 columns q0, q0+1
    const float4* hrow = reinterpret_cast<const float4*>(&g_h[(size_t)n * HIDDEN]);
    #pragma unroll
    for (int kq = 0; kq < HIDDEN / 4; kq++) {
        float4 h4 = __ldg(&hrow[kq]);
        float hv[4] = {fmaxf(h4.x, 0.f), fmaxf(h4.y, 0.f),
                       fmaxf(h4.z, 0.f), fmaxf(h4.w, 0.f)};
        #pragma unroll
        for (int j = 0; j < 4; j++) {
            int k = kq * 4 + j;
            #pragma unroll
            for (int q = 0; q < 2; q++) {
                float4 w4 = Ws[k][q0 + q];
                acc[q * 4 + 0] = fmaf(hv[j], w4.x, acc[q * 4 + 0]);
                acc[q * 4 + 1] = fmaf(hv[j], w4.y, acc[q * 4 + 1]);
                acc[q * 4 + 2] = fmaf(hv[j], w4.z, acc[q * 4 + 2]);
                acc[q * 4 + 3] = fmaf(hv[j], w4.w, acc[q * 4 + 3]);
            }
        }
    }
    float4* o = reinterpret_cast<float4*>(&g_z[(size_t)n * N_CLASS + half * 8]);
    o[0] = make_float4(acc[0], acc[1], acc[2], acc[3]);
    o[1] = make_float4(acc[4], acc[5], acc[6], acc[7]);
}

// ---------------------------------------------------------------------------
// SpMM2: g_l[dst] += ew * g_z[src]   (16 classes, 4 lanes/edge, float4 RED)
// Round-11 proven version.                                        (#5)
// ---------------------------------------------------------------------------
__global__ __launch_bounds__(256)
void spmm2_kernel(const int* __restrict__ src, const int* __restrict__ dst,
                  const float* __restrict__ ew) {
    int t = blockIdx.x * blockDim.x + threadIdx.x;
    int e = t >> 2;
    int c = (t & 3) << 2;
    if (e >= N_EDGES) return;
    int s   = __ldg(&src[e]);
    int d   = __ldg(&dst[e]);
    float w = __ldg(&ew[e]);
    float4 v = *reinterpret_cast<const float4*>(&g_z[(size_t)s * N_CLASS + c]);
    red_add_v4(&g_l[(size_t)d * N_CLASS + c],
               make_float4(v.x * w, v.y * w, v.z * w, v.w * w));
}

// ---------------------------------------------------------------------------
// Softmax over 16 classes, one thread per node.                   (#6)
// ---------------------------------------------------------------------------
__global__ __launch_bounds__(256)
void softmax_kernel(float* __restrict__ out) {
    int n = blockIdx.x * blockDim.x + threadIdx.x;
    if (n >= N_NODES) return;
    float v[N_CLASS];
    const float4* p = reinterpret_cast<const float4*>(&g_l[(size_t)n * N_CLASS]);
    #pragma unroll
    for (int i = 0; i < 4; i++) {
        float4 q = p[i];
        v[i * 4 + 0] = q.x; v[i * 4 + 1] = q.y; v[i * 4 + 2] = q.z; v[i * 4 + 3] = q.w;
    }
    float m = v[0];
    #pragma unroll
    for (int i = 1; i < N_CLASS; i++) m = fmaxf(m, v[i]);
    float sum = 0.f;
    #pragma unroll
    for (int i = 0; i < N_CLASS; i++) { v[i] = __expf(v[i] - m); sum += v[i]; }
    float inv = 1.f / sum;
    float4* o = reinterpret_cast<float4*>(&out[(size_t)n * N_CLASS]);
    #pragma unroll
    for (int i = 0; i < 4; i++) {
        o[i] = make_float4(v[i * 4] * inv, v[i * 4 + 1] * inv,
                           v[i * 4 + 2] * inv, v[i * 4 + 3] * inv);
    }
}

// ---------------------------------------------------------------------------
extern "C" void kernel_launch(void* const* d_in, const int* in_sizes, int n_in,
                              void* d_out, int out_size) {
    const float* x   = (const float*)d_in[0];
    const int*   src = (const int*)  d_in[1];
    const int*   dst = (const int*)  d_in[2];
    const float* ew  = (const float*)d_in[3];
    const float* W1  = (const float*)d_in[4];
    const float* b1  = (const float*)d_in[5];
    const float* W2  = (const float*)d_in[6];
    const float* b2  = (const float*)d_in[7];
    float* out = (float*)d_out;

    // #1: fused prep (bias broadcasts + W1 bf16 split)
    prep_kernel<<<(N_NODES * HIDDEN + 255) / 256, 256>>>(b1, b2, W1);

    // #2: GEMM1 (round-11 build)
    gemm1_kernel<<<(N_NODES + RBM - 1) / RBM, 256>>>(x);

    // #3: SpMM1
    {
        long long threads = (long long)N_EDGES * 16;
        spmm1_kernel<<<(unsigned)((threads + 255) / 256), 256>>>(src, dst, ew);
    }
    // #4: GEMM2 output-split  (profiled slot)
    {
        int total = N_NODES * 2;
        gemm2_kernel<<<(total + 255) / 256, 256>>>(W2);
    }
    // #5: SpMM2
    {
        long long threads = (long long)N_EDGES * 4;
        spmm2_kernel<<<(unsigned)((threads + 255) / 256), 256>>>(src, dst, ew);
    }
    // #6: Softmax
    softmax_kernel<<<(N_NODES + 255) / 256, 256>>>(out);
}

// round 16
// speedup vs baseline: 1.2251x; 1.1327x over previous
#include <cuda_runtime.h>
#include <cuda_bf16.h>
#include <cstdint>

#define N_NODES 50000
#define N_EDGES 800000
#define IN_FEAT 512
#define HIDDEN  64
#define N_CLASS 16

#define KC2   32                    // K per chunk
#define KPAD  40                    // padded row (80B stride -> conflict-free LDSM)
#define RBM   64                    // rows per CTA in gemm1
#define NCHUNK2 (IN_FEAT / KC2)     // 16
#define EHALF (N_EDGES / 2)         // 400000

// Scratch (device globals — no allocation allowed)
__device__ float g_h0[N_NODES * HIDDEN];   // x @ W1
__device__ float g_h [N_NODES * HIDDEN];   // A @ h0 + b1 (pre-relu)
__device__ float g_z [N_NODES * N_CLASS];  // relu(h) @ W2
__device__ float g_l [N_NODES * N_CLASS];  // A @ z + b2 (logits)
__device__ __nv_bfloat16 g_w1t_hi[HIDDEN * IN_FEAT];  // W1^T hi, [n][k]
__device__ __nv_bfloat16 g_w1t_lo[HIDDEN * IN_FEAT];  // W1^T residual

__device__ __forceinline__ void red_add_v4(float* p, float4 v) {
    asm volatile("red.global.add.v4.f32 [%0], {%1,%2,%3,%4};"
                 :: "l"(p), "f"(v.x), "f"(v.y), "f"(v.z), "f"(v.w)
                 : "memory");
}

__device__ __forceinline__ uint32_t pack_bf2(float v0, float v1) {
    uint32_t r;
    asm("cvt.rn.bf16x2.f32 %0, %1, %2;" : "=r"(r) : "f"(v1), "f"(v0));
    return r;
}
__device__ __forceinline__ float bf_round(float v) {
    return __bfloat162float(__float2bfloat16_rn(v));
}

__device__ __forceinline__ uint32_t smem_u32(const void* p) {
    uint32_t a;
    asm("{ .reg .u64 t; cvta.to.shared.u64 t, %1; cvt.u32.u64 %0, t; }"
        : "=r"(a) : "l"(p));
    return a;
}

__device__ __forceinline__ void mma_bf16(float* d, const uint32_t* a,
                                         uint32_t b0, uint32_t b1) {
    asm("mma.sync.aligned.m16n8k16.row.col.f32.bf16.bf16.f32 "
        "{%0,%1,%2,%3}, {%4,%5,%6,%7}, {%8,%9}, {%0,%1,%2,%3};"
        : "+f"(d[0]), "+f"(d[1]), "+f"(d[2]), "+f"(d[3])
        : "r"(a[0]), "r"(a[1]), "r"(a[2]), "r"(a[3]), "r"(b0), "r"(b1));
}

#define LDSM4(r0, r1, r2, r3, addr) \
    asm volatile("ldmatrix.sync.aligned.m8n8.x4.shared.b16 {%0,%1,%2,%3}, [%4];" \
                 : "=r"(r0), "=r"(r1), "=r"(r2), "=r"(r3) : "r"(addr))

// ---------------------------------------------------------------------------
// prep: g_h <- b1 broadcast, g_l <- b2 broadcast, W1 -> bf16 hi/lo transpose
// ---------------------------------------------------------------------------
__global__ void prep_kernel(const float* __restrict__ b1,
                            const float* __restrict__ b2,
                            const float* __restrict__ W1) {
    int i = blockIdx.x * blockDim.x + threadIdx.x;
    if (i < N_NODES * HIDDEN) g_h[i] = b1[i & (HIDDEN - 1)];
    if (i < N_NODES * N_CLASS) g_l[i] = b2[i & (N_CLASS - 1)];
    if (i < IN_FEAT * HIDDEN) {
        int k = i >> 6;
        int n = i & 63;
        float v = W1[i];
        __nv_bfloat16 h = __float2bfloat16_rn(v);
        float r = v - __bfloat162float(h);
        g_w1t_hi[(size_t)n * IN_FEAT + k] = h;
        g_w1t_lo[(size_t)n * IN_FEAT + k] = __float2bfloat16_rn(r);
    }
}

// ---------------------------------------------------------------------------
// GEMM1: g_h0 = x @ W1  via mma.sync bf16 (3-term split) + ldmatrix
// CTA: 256 thr = 8 warps. Tile M=64, N=64. grid=782.   (round-11 build)
// ---------------------------------------------------------------------------
__global__ __launch_bounds__(256, 3)
void gemm1_kernel(const float* __restrict__ x) {
    __shared__ __align__(16) __nv_bfloat16 Ah[2][RBM * KPAD];     // 2x5 KB
    __shared__ __align__(16) __nv_bfloat16 Al[2][RBM * KPAD];     // 2x5 KB
    __shared__ __align__(16) __nv_bfloat16 Bh[2][HIDDEN * KPAD];  // 2x5 KB
    __shared__ __align__(16) __nv_bfloat16 Bl[2][HIDDEN * KPAD];  // 2x5 KB

    const int tid  = threadIdx.x;
    const int wid  = tid >> 5;
    const int lane = tid & 31;
    const int g    = lane >> 2;
    const int tig  = lane & 3;
    const int rg   = wid & 3;
    const int cg   = wid >> 2;
    const int row0 = blockIdx.x * RBM;

    const int arow = tid >> 2;
    const int aseg = tid & 3;
    int grow = row0 + arow;
    if (grow >= N_NODES) grow = N_NODES - 1;
    const float* xrow = x + (size_t)grow * IN_FEAT + aseg * 8;

    const int bn  = tid >> 2;
    const int bsg = tid & 3;

    const uint32_t bufStride = RBM * KPAD * 2;   // 5120 B
    const int a_row_l = rg * 16 + (lane & 7) + ((lane >> 3) & 1) * 8;
    const int a_koff  = (lane >> 4) * 8;
    const uint32_t aAh = smem_u32(&Ah[0][0]) + (a_row_l * KPAD + a_koff) * 2;
    const uint32_t aAl = smem_u32(&Al[0][0]) + (a_row_l * KPAD + a_koff) * 2;
    uint32_t aBh[2], aBl[2];
    #pragma unroll
    for (int p = 0; p < 2; p++) {
        int nrow = (cg * 4 + 2 * p + (lane >> 4)) * 8 + (lane & 7);
        int koff = ((lane >> 3) & 1) * 8;
        aBh[p] = smem_u32(&Bh[0][0]) + (nrow * KPAD + koff) * 2;
        aBl[p] = smem_u32(&Bl[0][0]) + (nrow * KPAD + koff) * 2;
    }

    float4 xr[2];
    uint4  bwh, bwl;

    auto ld = [&](int c) {
        const int k0 = c * KC2;
        xr[0] = __ldg(reinterpret_cast<const float4*>(&xrow[k0]));
        xr[1] = __ldg(reinterpret_cast<const float4*>(&xrow[k0 + 4]));
        bwh = *reinterpret_cast<const uint4*>(
                  &g_w1t_hi[(size_t)bn * IN_FEAT + k0 + bsg * 8]);
        bwl = *reinterpret_cast<const uint4*>(
                  &g_w1t_lo[(size_t)bn * IN_FEAT + k0 + bsg * 8]);
    };
    auto st = [&](int b) {
        #pragma unroll
        for (int q = 0; q < 2; q++) {
            float4 v = xr[q];
            uint2 hv = make_uint2(pack_bf2(v.x, v.y), pack_bf2(v.z, v.w));
            uint2 lv = make_uint2(
                pack_bf2(v.x - bf_round(v.x), v.y - bf_round(v.y)),
                pack_bf2(v.z - bf_round(v.z), v.w - bf_round(v.w)));
            int eo = arow * KPAD + aseg * 8 + q * 4;
            *reinterpret_cast<uint2*>(&Ah[b][eo]) = hv;
            *reinterpret_cast<uint2*>(&Al[b][eo]) = lv;
        }
        *reinterpret_cast<uint4*>(&Bh[b][bn * KPAD + bsg * 8]) = bwh;
        *reinterpret_cast<uint4*>(&Bl[b][bn * KPAD + bsg * 8]) = bwl;
    };

    float d[4][4] = {};

    ld(0); st(0);
    __syncthreads();

    for (int c = 0; c < NCHUNK2; c++) {
        const int cb = c & 1;
        const uint32_t bo = cb * bufStride;
        if (c + 1 < NCHUNK2) ld(c + 1);

        #pragma unroll
        for (int ks = 0; ks < 2; ks++) {
            const uint32_t ko = ks * 32;
            uint32_t ah[4], al[4];
            LDSM4(ah[0], ah[1], ah[2], ah[3], aAh + bo + ko);
            LDSM4(al[0], al[1], al[2], al[3], aAl + bo + ko);
            #pragma unroll
            for (int p = 0; p < 2; p++) {
                uint32_t bh0, bh1, bh2, bh3, bl0, bl1, bl2, bl3;
                LDSM4(bh0, bh1, bh2, bh3, aBh[p] + bo + ko);
                LDSM4(bl0, bl1, bl2, bl3, aBl[p] + bo + ko);
                mma_bf16(d[2*p],     ah, bh0, bh1);
                mma_bf16(d[2*p],     al, bh0, bh1);
                mma_bf16(d[2*p],     ah, bl0, bl1);
                mma_bf16(d[2*p + 1], ah, bh2, bh3);
                mma_bf16(d[2*p + 1], al, bh2, bh3);
                mma_bf16(d[2*p + 1], ah, bl2, bl3);
            }
        }

        if (c + 1 < NCHUNK2) st(1 - cb);
        __syncthreads();
    }

    {
        int r0 = row0 + rg * 16 + g;
        int r1 = r0 + 8;
        #pragma unroll
        for (int j = 0; j < 4; j++) {
            int col = (cg * 4 + j) * 8 + 2 * tig;
            if (r0 < N_NODES)
                *reinterpret_cast<float2*>(&g_h0[(size_t)r0 * HIDDEN + col]) =
                    make_float2(d[j][0], d[j][1]);
            if (r1 < N_NODES)
                *reinterpret_cast<float2*>(&g_h0[(size_t)r1 * HIDDEN + col]) =
                    make_float2(d[j][2], d[j][3]);
        }
    }
}

// ---------------------------------------------------------------------------
// SpMM1: g_h[dst] += ew * g_h0[src]
// 16 lanes/edge, 2 edges per thread (e, e+EHALF) -> MLP=2 per thread.
// ---------------------------------------------------------------------------
__global__ __launch_bounds__(256)
void spmm1_kernel(const int* __restrict__ src, const int* __restrict__ dst,
                  const float* __restrict__ ew) {
    int t = blockIdx.x * blockDim.x + threadIdx.x;
    int e0 = t >> 4;
    int f  = (t & 15) << 2;
    if (e0 >= EHALF) return;
    int e1 = e0 + EHALF;

    int s0 = __ldg(&src[e0]);
    int s1 = __ldg(&src[e1]);
    int d0 = __ldg(&dst[e0]);
    int d1 = __ldg(&dst[e1]);
    float w0 = __ldg(&ew[e0]);
    float w1 = __ldg(&ew[e1]);

    float4 v0 = *reinterpret_cast<const float4*>(&g_h0[(size_t)s0 * HIDDEN + f]);
    float4 v1 = *reinterpret_cast<const float4*>(&g_h0[(size_t)s1 * HIDDEN + f]);

    red_add_v4(&g_h[(size_t)d0 * HIDDEN + f],
               make_float4(v0.x * w0, v0.y * w0, v0.z * w0, v0.w * w0));
    red_add_v4(&g_h[(size_t)d1 * HIDDEN + f],
               make_float4(v1.x * w1, v1.y * w1, v1.z * w1, v1.w * w1));
}

// ---------------------------------------------------------------------------
// GEMM2: g_z = relu(g_h) @ W2   (50000x64 @ 64x16)
// Output-split: thread (n, half) computes classes half*8..half*8+7.
// ---------------------------------------------------------------------------
__global__ __launch_bounds__(256)
void gemm2_kernel(const float* __restrict__ W2) {
    __shared__ float4 Ws[HIDDEN][N_CLASS / 4];   // 4 KB

    const int tid = threadIdx.x;
    {
        int kk = tid >> 2, qq = tid & 3;
        Ws[kk][qq] = reinterpret_cast<const float4*>(&W2[(size_t)kk * N_CLASS])[qq];
    }
    __syncthreads();

    int t2   = blockIdx.x * 256 + tid;
    int n    = t2 >> 1;
    int half = t2 & 1;
    if (n >= N_NODES) return;

    float acc[8] = {};
    const int q0 = half * 2;
    const float4* hrow = reinterpret_cast<const float4*>(&g_h[(size_t)n * HIDDEN]);
    #pragma unroll
    for (int kq = 0; kq < HIDDEN / 4; kq++) {
        float4 h4 = __ldg(&hrow[kq]);
        float hv[4] = {fmaxf(h4.x, 0.f), fmaxf(h4.y, 0.f),
                       fmaxf(h4.z, 0.f), fmaxf(h4.w, 0.f)};
        #pragma unroll
        for (int j = 0; j < 4; j++) {
            int k = kq * 4 + j;
            #pragma unroll
            for (int q = 0; q < 2; q++) {
                float4 w4 = Ws[k][q0 + q];
                acc[q * 4 + 0] = fmaf(hv[j], w4.x, acc[q * 4 + 0]);
                acc[q * 4 + 1] = fmaf(hv[j], w4.y, acc[q * 4 + 1]);
                acc[q * 4 + 2] = fmaf(hv[j], w4.z, acc[q * 4 + 2]);
                acc[q * 4 + 3] = fmaf(hv[j], w4.w, acc[q * 4 + 3]);
            }
        }
    }
    float4* o = reinterpret_cast<float4*>(&g_z[(size_t)n * N_CLASS + half * 8]);
    o[0] = make_float4(acc[0], acc[1], acc[2], acc[3]);
    o[1] = make_float4(acc[4], acc[5], acc[6], acc[7]);
}

// ---------------------------------------------------------------------------
// SpMM2: g_l[dst] += ew * g_z[src]
// 4 lanes/edge, 2 edges per thread (e, e+EHALF) -> MLP=2 per thread.
// ---------------------------------------------------------------------------
__global__ __launch_bounds__(256)
void spmm2_kernel(const int* __restrict__ src, const int* __restrict__ dst,
                  const float* __restrict__ ew) {
    int t = blockIdx.x * blockDim.x + threadIdx.x;
    int e0 = t >> 2;
    int c  = (t & 3) << 2;
    if (e0 >= EHALF) return;
    int e1 = e0 + EHALF;

    int s0 = __ldg(&src[e0]);
    int s1 = __ldg(&src[e1]);
    int d0 = __ldg(&dst[e0]);
    int d1 = __ldg(&dst[e1]);
    float w0 = __ldg(&ew[e0]);
    float w1 = __ldg(&ew[e1]);

    float4 v0 = *reinterpret_cast<const float4*>(&g_z[(size_t)s0 * N_CLASS + c]);
    float4 v1 = *reinterpret_cast<const float4*>(&g_z[(size_t)s1 * N_CLASS + c]);

    red_add_v4(&g_l[(size_t)d0 * N_CLASS + c],
               make_float4(v0.x * w0, v0.y * w0, v0.z * w0, v0.w * w0));
    red_add_v4(&g_l[(size_t)d1 * N_CLASS + c],
               make_float4(v1.x * w1, v1.y * w1, v1.z * w1, v1.w * w1));
}

// ---------------------------------------------------------------------------
// Softmax over 16 classes, one thread per node.
// ---------------------------------------------------------------------------
__global__ __launch_bounds__(256)
void softmax_kernel(float* __restrict__ out) {
    int n = blockIdx.x * blockDim.x + threadIdx.x;
    if (n >= N_NODES) return;
    float v[N_CLASS];
    const float4* p = reinterpret_cast<const float4*>(&g_l[(size_t)n * N_CLASS]);
    #pragma unroll
    for (int i = 0; i < 4; i++) {
        float4 q = p[i];
        v[i * 4 + 0] = q.x; v[i * 4 + 1] = q.y; v[i * 4 + 2] = q.z; v[i * 4 + 3] = q.w;
    }
    float m = v[0];
    #pragma unroll
    for (int i = 1; i < N_CLASS; i++) m = fmaxf(m, v[i]);
    float sum = 0.f;
    #pragma unroll
    for (int i = 0; i < N_CLASS; i++) { v[i] = __expf(v[i] - m); sum += v[i]; }
    float inv = 1.f / sum;
    float4* o = reinterpret_cast<float4*>(&out[(size_t)n * N_CLASS]);
    #pragma unroll
    for (int i = 0; i < 4; i++) {
        o[i] = make_float4(v[i * 4] * inv, v[i * 4 + 1] * inv,
                           v[i * 4 + 2] * inv, v[i * 4 + 3] * inv);
    }
}

// ---------------------------------------------------------------------------
extern "C" void kernel_launch(void* const* d_in, const int* in_sizes, int n_in,
                              void* d_out, int out_size) {
    const float* x   = (const float*)d_in[0];
    const int*   src = (const int*)  d_in[1];
    const int*   dst = (const int*)  d_in[2];
    const float* ew  = (const float*)d_in[3];
    const float* W1  = (const float*)d_in[4];
    const float* b1  = (const float*)d_in[5];
    const float* W2  = (const float*)d_in[6];
    const float* b2  = (const float*)d_in[7];
    float* out = (float*)d_out;

    // #1: fused prep (bias broadcasts + W1 bf16 split)
    prep_kernel<<<(N_NODES * HIDDEN + 255) / 256, 256>>>(b1, b2, W1);

    // #2: GEMM1
    gemm1_kernel<<<(N_NODES + RBM - 1) / RBM, 256>>>(x);

    // #3: SpMM1 (2 edges/thread)
    {
        long long threads = (long long)EHALF * 16;
        spmm1_kernel<<<(unsigned)((threads + 255) / 256), 256>>>(src, dst, ew);
    }
    // #4: GEMM2 output-split  (profiled slot)
    {
        int total = N_NODES * 2;
        gemm2_kernel<<<(total + 255) / 256, 256>>>(W2);
    }
    // #5: SpMM2 (2 edges/thread)
    {
        long long threads = (long long)EHALF * 4;
        spmm2_kernel<<<(unsigned)((threads + 255) / 256), 256>>>(src, dst, ew);
    }
    // #6: Softmax
    softmax_kernel<<<(N_NODES + 255) / 256, 256>>>(out);
}